// round 7
// baseline (speedup 1.0000x reference)
#include <cuda_runtime.h>
#include <math.h>
#include <float.h>

#define BB 2
#define MM 256
#define DD 256
#define DE 64
#define TP 257
#define WM_RS 320   // Wm row stride in floats (DE + DD)

typedef unsigned long long u64;

__device__ __forceinline__ u64 ffma2(u64 a, u64 b, u64 c) {
    u64 d;
    asm("fma.rn.f32x2 %0, %1, %2, %3;" : "=l"(d) : "l"(a), "l"(b), "l"(c));
    return d;
}
__device__ __forceinline__ float2 unpack2(u64 p) {
    float2 r;
    asm("mov.b64 {%0, %1}, %2;" : "=f"(r.x), "=f"(r.y) : "l"(p));
    return r;
}

// ---------------- scratch ----------------
__device__ __align__(256) float g_Wc   [DD*DD];   // [k][d] combined Wz^T @ Wmf^T
__device__ __align__(256) float g_u    [DD];      // folded nfdot weight
__device__ __align__(256) float g_nfb  [DD];      // folded nfproj bias
__device__ __align__(256) float g_c1[1];          // folded nfdot bias
__device__ __align__(256) float g_nfproj[BB*MM*DD];
__device__ __align__(256) float g_nfdot [BB*MM];
__device__ __align__(256) float g_f0q  [BB*16*DD]; // zf[0, 1+i_q] per query
__device__ __align__(256) float g_fused[BB*16*DD];

// ---------------- reductions (256 threads) ----------------
__device__ __forceinline__ float bsum256(float v, float* red) {
    #pragma unroll
    for (int o = 16; o > 0; o >>= 1) v += __shfl_down_sync(0xffffffffu, v, o);
    if ((threadIdx.x & 31) == 0) red[threadIdx.x >> 5] = v;
    __syncthreads();
    if (threadIdx.x < 8) {
        v = red[threadIdx.x];
        #pragma unroll
        for (int o = 4; o > 0; o >>= 1) v += __shfl_down_sync(0xffu, v, o);
        if (threadIdx.x == 0) red[0] = v;
    }
    __syncthreads();
    float r = red[0];
    __syncthreads();
    return r;
}

__device__ __forceinline__ float bmax256(float v, float* red) {
    #pragma unroll
    for (int o = 16; o > 0; o >>= 1) v = fmaxf(v, __shfl_down_sync(0xffffffffu, v, o));
    if ((threadIdx.x & 31) == 0) red[threadIdx.x >> 5] = v;
    __syncthreads();
    if (threadIdx.x < 8) {
        v = red[threadIdx.x];
        #pragma unroll
        for (int o = 4; o > 0; o >>= 1) v = fmaxf(v, __shfl_down_sync(0xffu, v, o));
        if (threadIdx.x == 0) red[0] = v;
    }
    __syncthreads();
    float r = red[0];
    __syncthreads();
    return r;
}

// ---------------- kA: Wc / u / nfb / c + f0q rows + copy ----------------
// grid 97: [0,64) Wc tiles, 64 u+c, [65,81) f0q, [81,97) copy
__global__ __launch_bounds__(256) void kA(const float* __restrict__ features,
                                          const float* __restrict__ Wz,
                                          const float* __restrict__ bz,
                                          const float* __restrict__ Wa,
                                          const float* __restrict__ Wm,
                                          const int*   __restrict__ asp_start,
                                          float* __restrict__ out)
{
    const int bid = blockIdx.x, tid = threadIdx.x;

    if (bid < 64) {
        // ---- Wc[k][d0..d0+3] = sum_j Wz[j][k] * Wm[d][DE+j];  nfb[d0..d0+3]
        const int d0 = bid * 4;
        __shared__ __align__(16) float wmr[4][DD];
        for (int idx = tid; idx < 4*DD; idx += 256) {
            const int r = idx >> 8, j = idx & 255;
            wmr[r][j] = Wm[(size_t)(d0 + r)*WM_RS + DE + j];
        }
        __syncthreads();

        if (tid < 128) {   // nfb via warps 0..3
            const int r = tid >> 5, lane = tid & 31;
            float s = 0.f;
            #pragma unroll
            for (int t = 0; t < 8; t++) s = fmaf(bz[lane + t*32], wmr[r][lane + t*32], s);
            #pragma unroll
            for (int o = 16; o > 0; o >>= 1) s += __shfl_down_sync(0xffffffffu, s, o);
            if (lane == 0) g_nfb[d0 + r] = s;
        }

        const int k = tid;
        float a0 = 0.f, a1 = 0.f, a2 = 0.f, a3 = 0.f;
        #pragma unroll 4
        for (int j = 0; j < DD; j++) {
            const float wz = Wz[(size_t)j*DD + k];   // coalesced
            a0 = fmaf(wz, wmr[0][j], a0);
            a1 = fmaf(wz, wmr[1][j], a1);
            a2 = fmaf(wz, wmr[2][j], a2);
            a3 = fmaf(wz, wmr[3][j], a3);
        }
        *(float4*)&g_Wc[(size_t)k*DD + d0] = make_float4(a0, a1, a2, a3);
    }
    else if (bid == 64) {
        // ---- u[k] = sum_j Wz[j][k] * Wa[DE+j];  c = bz . Wa[DE:]
        __shared__ __align__(16) float was[DD];
        __shared__ float red[8];
        was[tid] = Wa[DE + tid];
        __syncthreads();
        const int k = tid;
        float a = 0.f;
        #pragma unroll 4
        for (int j = 0; j < DD; j++)
            a = fmaf(Wz[(size_t)j*DD + k], was[j], a);
        g_u[k] = a;
        const float c = bsum256(bz[tid] * was[tid], red);
        if (tid == 0) g_c1[0] = c;
    }
    else if (bid < 81) {
        // ---- f0q: 2 query rows of zf[0, 1+i]
        const int qb = (bid - 65) * 2;
        __shared__ __align__(16) float xq[2][DD];
        for (int idx = tid; idx < 2*DD; idx += 256) {
            const int s = idx >> 8, d = idx & 255;
            const int q = qb + s;
            const int i = asp_start[q >> 4] + (q & 15);
            xq[s][d] = features[(size_t)(1 + i)*DD + d];   // batch 0 always
        }
        __syncthreads();

        const int grp = tid >> 3, l8 = tid & 7;
        #pragma unroll
        for (int s = 0; s < 2; s++) {
            const float4* x4 = (const float4*)xq[s];
            #pragma unroll
            for (int rr = 0; rr < 8; rr++) {
                const int dr = grp*8 + rr;
                const float4* w4 = (const float4*)(Wz + (size_t)dr*DD);
                float o = 0.f;
                #pragma unroll
                for (int t = 0; t < 8; t++) {
                    const int idx = t*8 + l8;
                    const float4 w = w4[idx];
                    const float4 x = x4[idx];
                    o = fmaf(w.x, x.x, o); o = fmaf(w.y, x.y, o);
                    o = fmaf(w.z, x.z, o); o = fmaf(w.w, x.w, o);
                }
                o += __shfl_down_sync(0xffffffffu, o, 4, 8);
                o += __shfl_down_sync(0xffffffffu, o, 2, 8);
                o += __shfl_down_sync(0xffffffffu, o, 1, 8);
                if (l8 == 0) g_f0q[(qb + s)*DD + dr] = o + bz[dr];
            }
        }
    }
    else {
        // ---- copy features -> out
        const int cb = bid - 81;
        const float4* src = (const float4*)features;
        float4* d4 = (float4*)out;
        const int total = BB*TP*DD/4;   // 32896
        for (int x = cb*256 + tid; x < total; x += 16*256) d4[x] = src[x];
    }
}

// ---------------- kB: nfproj = X @ Wc + nfb ;  nfdot = X.u + c ----------------
// grid 256: dc = bid&1 (d half), rg = bid>>1 (4-row group); 256 threads:
// dl = tid&127 -> d = dc*128+dl ; rpair = tid>>7 -> rows rpair*2, rpair*2+1
__global__ __launch_bounds__(256) void kB(const float* __restrict__ features)
{
    const int bid = blockIdx.x, tid = threadIdx.x;
    const int dc = bid & 1, rg = bid >> 1;
    const int b = rg >> 6, m0 = (rg & 63) << 2;

    __shared__ __align__(16) float xs[4][DD];
    __shared__ float red[8];

    {
        const int g = tid >> 6, q = tid & 63;
        ((float4*)xs[g])[q] = ((const float4*)&features[((size_t)b*TP + 1 + m0 + g)*DD])[q];
    }
    __syncthreads();

    if (dc == 0) {
        const float uv = g_u[tid];
        const float c  = g_c1[0];
        #pragma unroll
        for (int r = 0; r < 4; r++) {
            const float tot = bsum256(xs[r][tid] * uv, red);
            if (tid == 0) g_nfdot[b*MM + m0 + r] = tot + c;
        }
    }

    const int dl = tid & 127, rpair = tid >> 7;
    const int d  = dc*128 + dl;
    const int r0 = rpair*2;

    float a0 = 0.f, a1 = 0.f;
    #pragma unroll 4
    for (int k = 0; k < DD; k += 4) {
        const float w0 = g_Wc[(size_t)(k+0)*DD + d];
        const float w1 = g_Wc[(size_t)(k+1)*DD + d];
        const float w2 = g_Wc[(size_t)(k+2)*DD + d];
        const float w3 = g_Wc[(size_t)(k+3)*DD + d];
        const float4 xa = *(const float4*)&xs[r0][k];
        const float4 xb = *(const float4*)&xs[r0+1][k];
        a0 = fmaf(xa.x, w0, a0); a0 = fmaf(xa.y, w1, a0);
        a0 = fmaf(xa.z, w2, a0); a0 = fmaf(xa.w, w3, a0);
        a1 = fmaf(xb.x, w0, a1); a1 = fmaf(xb.y, w1, a1);
        a1 = fmaf(xb.z, w2, a1); a1 = fmaf(xb.w, w3, a1);
    }
    const float nb = g_nfb[d];
    g_nfproj[((size_t)b*MM + m0 + r0    )*DD + d] = a0 + nb;
    g_nfproj[((size_t)b*MM + m0 + r0 + 1)*DD + d] = a1 + nb;
}

// ---------------- k2b: scores + softmax + message (per d-chunk) ----------------
// grid (4 dchunks, 32 queries), 256 threads
__global__ __launch_bounds__(256) void k2b(const float* __restrict__ dep,
                                           const int*   __restrict__ adj,
                                           const int*   __restrict__ asp_start,
                                           const float* __restrict__ Wa,
                                           const float* __restrict__ Wm)
{
    const int dc = blockIdx.x;          // 0..3
    const int q  = blockIdx.y;          // 0..31
    const int b  = q >> 4, slot = q & 15;
    const int i  = asp_start[b] + slot;

    const int tid = threadIdx.x;

    __shared__ __align__(16) float dsr[96][68];
    __shared__ float s_l[2*MM];
    __shared__ float wn [2*MM];
    __shared__ int   list[2*MM];
    __shared__ float wdep[DE];
    __shared__ float fpart[4][64];
    __shared__ float red[8];
    __shared__ int   cnt;

    if (tid == 0) cnt = 0;
    if (tid < DE) wdep[tid] = Wa[tid];
    __syncthreads();

    const float aspdot = bsum256(g_f0q[q*DD + tid] * Wa[DE + DD + tid], red);

    if (adj[((size_t)b*MM + i)*MM + tid] != 0) {
        int p = atomicAdd(&cnt, 1); list[p] = tid;
    }
    if (adj[((size_t)b*MM + tid)*MM + i] != 0) {
        int p = atomicAdd(&cnt, 1); list[p] = tid + MM;
    }
    __syncthreads();
    const int n = cnt;

    // ---- scores (chunked staging) ----
    for (int c0 = 0; c0 < n; c0 += 96) {
        const int nc = min(96, n - c0);
        __syncthreads();
        for (int idx = tid; idx < nc*16; idx += 256) {
            const int j = idx >> 4, e4 = idx & 15;
            const int kk = list[c0 + j];
            const int row = (kk < MM) ? i : (kk - MM);
            const int col = (kk < MM) ? kk : i;
            *(float4*)&dsr[j][e4*4] =
                ((const float4*)dep)[(((size_t)b*MM + row)*MM + col)*16 + e4];
        }
        __syncthreads();
        for (int j = tid; j < nc; j += 256) {
            float s = 0.f;
            #pragma unroll
            for (int e4 = 0; e4 < 16; e4++) {
                const float4 v = *(const float4*)&dsr[j][e4*4];
                s = fmaf(v.x, wdep[4*e4+0], s); s = fmaf(v.y, wdep[4*e4+1], s);
                s = fmaf(v.z, wdep[4*e4+2], s); s = fmaf(v.w, wdep[4*e4+3], s);
            }
            const int kk = list[c0 + j];
            s += g_nfdot[b*MM + (kk & (MM-1))] + aspdot;
            s_l[c0 + j] = (s > 0.f) ? s : 0.01f * s;
        }
    }
    __syncthreads();

    // ---- softmax ----
    const float sv0 = (tid       < n) ? s_l[tid]       : -FLT_MAX;
    const float sv1 = (tid + 256 < n) ? s_l[tid + 256] : -FLT_MAX;
    const float smax = bmax256(fmaxf(sv0, sv1), red);
    const float e0 = (tid       < n) ? expf(sv0 - smax) : 0.f;
    const float e1 = (tid + 256 < n) ? expf(sv1 - smax) : 0.f;
    if (tid       < n) wn[tid]       = e0;
    if (tid + 256 < n) wn[tid + 256] = e1;
    const float inv = 1.f / bsum256(e0 + e1, red);

    // ---- message ----
    const int kg = tid >> 6, dl = tid & 63;
    const int d  = dc*64 + dl;

    u64 wp[32];
    {
        const ulonglong2* w2 = (const ulonglong2*)(Wm + (size_t)d*WM_RS);
        #pragma unroll
        for (int t2 = 0; t2 < 16; t2++) {
            const ulonglong2 v = w2[t2];
            wp[2*t2] = v.x; wp[2*t2 + 1] = v.y;
        }
    }

    float acc = 0.f;
    for (int c0 = 0; c0 < n; c0 += 96) {
        const int nc = min(96, n - c0);
        __syncthreads();
        for (int idx = tid; idx < nc*16; idx += 256) {
            const int j = idx >> 4, e4 = idx & 15;
            const int kk = list[c0 + j];
            const int row = (kk < MM) ? i : (kk - MM);
            const int col = (kk < MM) ? kk : i;
            *(float4*)&dsr[j][e4*4] =
                ((const float4*)dep)[(((size_t)b*MM + row)*MM + col)*16 + e4];
        }
        __syncthreads();
        for (int jl = kg; jl < nc; jl += 4) {
            const int pos = c0 + jl;
            const int kk  = list[pos];
            const float wk = wn[pos] * inv;
            const float mi = g_nfproj[((size_t)b*MM + (kk & (MM-1)))*DD + d];
            const ulonglong2* dr2 = (const ulonglong2*)&dsr[jl][0];
            u64 mA = 0, mB = 0, mC = 0, mD = 0;
            #pragma unroll
            for (int t2 = 0; t2 < 16; t2 += 2) {
                const ulonglong2 v0 = dr2[t2];
                const ulonglong2 v1 = dr2[t2 + 1];
                mA = ffma2(v0.x, wp[2*t2],     mA);
                mB = ffma2(v0.y, wp[2*t2 + 1], mB);
                mC = ffma2(v1.x, wp[2*t2 + 2], mC);
                mD = ffma2(v1.y, wp[2*t2 + 3], mD);
            }
            const float2 sA = unpack2(mA), sB = unpack2(mB);
            const float2 sC = unpack2(mC), sD = unpack2(mD);
            const float mval = mi + ((sA.x + sA.y) + (sB.x + sB.y))
                                  + ((sC.x + sC.y) + (sD.x + sD.y));
            acc = fmaf(wk, fmaxf(mval, 0.f), acc);
        }
    }

    fpart[kg][dl] = acc;
    __syncthreads();
    if (tid < 64)
        g_fused[q*DD + dc*64 + tid] =
            fpart[0][tid] + fpart[1][tid] + fpart[2][tid] + fpart[3][tid];
}

// ---------------- k2c: output head ----------------
// grid 256 = (32 q × 8 rowgroups); 256 threads = 32 Wh rows × 8 lanes
__global__ __launch_bounds__(256) void k2c(const int*   __restrict__ asp_start,
                                           const float* __restrict__ Wh,
                                           float*       __restrict__ out)
{
    const int q  = blockIdx.x >> 3;
    const int rg = blockIdx.x & 7;
    const int b  = q >> 4, slot = q & 15;
    const int i  = asp_start[b] + slot;

    const int tid = threadIdx.x;

    __shared__ __align__(16) float cat[2*DD];
    cat[tid]      = g_fused[q*DD + tid];
    cat[DD + tid] = g_f0q[q*DD + tid];
    __syncthreads();

    const int warp = tid >> 5, lane = tid & 31;
    const int rsub = lane >> 3, l8 = lane & 7;
    const int dr = rg*32 + warp*4 + rsub;

    const ulonglong2* wrow = (const ulonglong2*)(Wh + (size_t)dr*2*DD);
    const ulonglong2* cat2 = (const ulonglong2*)cat;

    u64 oA = 0, oB = 0;
    #pragma unroll
    for (int t = 0; t < 16; t++) {
        const int idx = t*8 + l8;
        const ulonglong2 wv = wrow[idx];
        const ulonglong2 cv = cat2[idx];
        oA = ffma2(wv.x, cv.x, oA);
        oB = ffma2(wv.y, cv.y, oB);
    }
    const float2 a = unpack2(oA), bb = unpack2(oB);
    float o = (a.x + a.y) + (bb.x + bb.y);
    o += __shfl_down_sync(0xffffffffu, o, 4, 8);
    o += __shfl_down_sync(0xffffffffu, o, 2, 8);
    o += __shfl_down_sync(0xffffffffu, o, 1, 8);
    if (l8 == 0)
        out[((size_t)b*TP + 1 + i)*DD + dr] = fmaxf(o, 0.f);
}

// ---------------- launcher ----------------
extern "C" void kernel_launch(void* const* d_in, const int* in_sizes, int n_in,
                              void* d_out, int out_size)
{
    const float* features  = (const float*)d_in[0];
    const float* dep       = (const float*)d_in[1];
    const int*   adj       = (const int*)  d_in[2];
    const int*   asp_start = (const int*)  d_in[3];
    const float* Wz        = (const float*)d_in[5];
    const float* bz        = (const float*)d_in[6];
    const float* Wa        = (const float*)d_in[7];
    const float* Wm        = (const float*)d_in[8];
    const float* Wh        = (const float*)d_in[9];
    float* out = (float*)d_out;

    kA <<<97, 256>>>(features, Wz, bz, Wa, Wm, asp_start, out);
    kB <<<256, 256>>>(features);
    k2b<<<dim3(4, 32), 256>>>(dep, adj, asp_start, Wa, Wm);
    k2c<<<256, 256>>>(asp_start, Wh, out);
}

// round 8
// speedup vs baseline: 1.3835x; 1.3835x over previous
#include <cuda_runtime.h>
#include <math.h>
#include <float.h>

#define BB 2
#define MM 256
#define DD 256
#define DE 64
#define TP 257
#define WM_RS 320
#define GRID 148
#define NT 256

typedef unsigned long long u64;

__device__ __forceinline__ u64 ffma2(u64 a, u64 b, u64 c) {
    u64 d; asm("fma.rn.f32x2 %0,%1,%2,%3;" : "=l"(d) : "l"(a), "l"(b), "l"(c)); return d;
}
__device__ __forceinline__ float2 unpack2(u64 p) {
    float2 r; asm("mov.b64 {%0,%1},%2;" : "=f"(r.x), "=f"(r.y) : "l"(p)); return r;
}

// ---------------- device scratch ----------------
__device__ __align__(256) float g_Wc[DD*DD];       // [k][d]
__device__ __align__(256) float g_u[DD];
__device__ __align__(256) float g_nfb[DD];
__device__ __align__(256) float g_c1[1];
__device__ __align__(256) float g_nfproj[BB*MM*DD];
__device__ __align__(256) float g_nfdot[BB*MM];
__device__ __align__(256) float g_f0q[32*DD];
__device__ __align__(256) float g_fused[32*DD];
__device__ __align__(256) int   g_list[32*512];
__device__ __align__(256) int   g_cnt[32];
__device__ unsigned g_ctr;   // monotonic grid-barrier counter (wrap-safe)

// ---------------- shared layout ----------------
struct SWc { float As[32][32]; float2 Bs[32][33]; };          // 4K + 8.25K
struct SP1 { float Xs[32][34]; float2 Ws[32][33]; };          // 4.25K + 8.25K
struct SP2 {
    float dsr[96][68];     // 25.5K
    float s_l[512];
    float wn[512];
    int   list[512];
    float wdep[DE];
    float fpart[4][64];
};
union USm {
    SWc wc; SP1 p1; SP2 p2;
    float misc[1024];
    float cat[512];
};

// ---------------- grid barrier ----------------
__device__ __forceinline__ void gbar() {
    __syncthreads();
    if (threadIdx.x == 0) {
        __threadfence();
        const unsigned v = atomicAdd(&g_ctr, 1u) + 1u;
        const unsigned target = ((v - 1u) / GRID + 1u) * GRID;
        unsigned cur;
        do {
            asm volatile("ld.acquire.gpu.u32 %0, [%1];" : "=r"(cur) : "l"(&g_ctr) : "memory");
        } while ((int)(cur - target) < 0);
    }
    __syncthreads();
}

// ---------------- block reductions (use s_red[8]) ----------------
__device__ __forceinline__ float bsum256(float v, float* red) {
    #pragma unroll
    for (int o = 16; o > 0; o >>= 1) v += __shfl_down_sync(0xffffffffu, v, o);
    if ((threadIdx.x & 31) == 0) red[threadIdx.x >> 5] = v;
    __syncthreads();
    if (threadIdx.x < 8) {
        v = red[threadIdx.x];
        #pragma unroll
        for (int o = 4; o > 0; o >>= 1) v += __shfl_down_sync(0xffu, v, o);
        if (threadIdx.x == 0) red[0] = v;
    }
    __syncthreads();
    float r = red[0];
    __syncthreads();
    return r;
}
__device__ __forceinline__ float bmax256(float v, float* red) {
    #pragma unroll
    for (int o = 16; o > 0; o >>= 1) v = fmaxf(v, __shfl_down_sync(0xffffffffu, v, o));
    if ((threadIdx.x & 31) == 0) red[threadIdx.x >> 5] = v;
    __syncthreads();
    if (threadIdx.x < 8) {
        v = red[threadIdx.x];
        #pragma unroll
        for (int o = 4; o > 0; o >>= 1) v = fmaxf(v, __shfl_down_sync(0xffu, v, o));
        if (threadIdx.x == 0) red[0] = v;
    }
    __syncthreads();
    float r = red[0];
    __syncthreads();
    return r;
}

// ---------------- the single persistent kernel ----------------
__global__ void __launch_bounds__(NT, 1) fused_all(
    const float* __restrict__ features, const float* __restrict__ dep,
    const int*   __restrict__ adj,      const int*   __restrict__ asp_start,
    const float* __restrict__ Wz,       const float* __restrict__ bz,
    const float* __restrict__ Wa,       const float* __restrict__ Wm,
    const float* __restrict__ Wh,       float* __restrict__ out)
{
    __shared__ __align__(16) USm sm;
    __shared__ float s_red[8];
    __shared__ int   s_w[8];

    const int bid = blockIdx.x, tid = threadIdx.x;

    // ================= P0 =================
    if (bid < 64) {
        // ---- Wc[k][d] = sum_j Wz[j][k] * Wm[d][64+j], 32x32 tile per block
        const int k0 = (bid >> 3) * 32, d0 = (bid & 7) * 32;
        const int ak = tid & 15, bd = tid >> 4;
        const int ldrow = tid >> 3, ldc = tid & 7;
        u64 acc0 = 0, acc1 = 0;
        for (int jc = 0; jc < 8; jc++) {
            const int j0 = jc * 32;
            const float4 av = *(const float4*)&Wz[(size_t)(j0 + ldrow)*DD + k0 + ldc*4];
            const float4 bv = *(const float4*)&Wm[(size_t)(d0 + ldrow)*WM_RS + DE + j0 + ldc*4];
            __syncthreads();
            *(float4*)&sm.wc.As[ldrow][ldc*4] = av;
            sm.wc.Bs[ldc*4+0][ldrow] = make_float2(bv.x, bv.x);
            sm.wc.Bs[ldc*4+1][ldrow] = make_float2(bv.y, bv.y);
            sm.wc.Bs[ldc*4+2][ldrow] = make_float2(bv.z, bv.z);
            sm.wc.Bs[ldc*4+3][ldrow] = make_float2(bv.w, bv.w);
            __syncthreads();
            #pragma unroll
            for (int j = 0; j < 32; j++) {
                const u64 a2 = *(const u64*)&sm.wc.As[j][2*ak];
                const u64 b0 = *(const u64*)&sm.wc.Bs[j][2*bd];
                const u64 b1 = *(const u64*)&sm.wc.Bs[j][2*bd+1];
                acc0 = ffma2(a2, b0, acc0);
                acc1 = ffma2(a2, b1, acc1);
            }
        }
        const float2 a0 = unpack2(acc0), a1 = unpack2(acc1);
        const int kA = k0 + 2*ak, dA = d0 + 2*bd;
        g_Wc[(size_t)kA*DD + dA]         = a0.x;
        g_Wc[(size_t)(kA+1)*DD + dA]     = a0.y;
        g_Wc[(size_t)kA*DD + dA + 1]     = a1.x;
        g_Wc[(size_t)(kA+1)*DD + dA + 1] = a1.y;
    }
    else if (bid == 64) {
        // ---- u[k] = sum_j Wz[j][k]*Wa[64+j];  c = bz . Wa[64:320]
        sm.misc[tid] = Wa[DE + tid];
        __syncthreads();
        float s = 0.f;
        for (int j0 = 0; j0 < DD; j0 += 32) {
            float wv[32];
            #pragma unroll
            for (int t = 0; t < 32; t++) wv[t] = Wz[(size_t)(j0+t)*DD + tid];
            #pragma unroll
            for (int t = 0; t < 32; t++) s = fmaf(wv[t], sm.misc[j0+t], s);
        }
        g_u[tid] = s;
        const float c = bsum256(bz[tid] * sm.misc[tid], s_red);
        if (tid == 0) g_c1[0] = c;
    }
    else if (bid == 65) {
        // ---- nfb[d] = sum_j bz[j]*Wm[d][64+j]  (8-lane dots)
        sm.misc[tid] = bz[tid];
        __syncthreads();
        const int rg8 = tid >> 3, l8 = tid & 7;
        for (int pass = 0; pass < 8; pass++) {
            const int dr = pass*32 + rg8;
            const float4* w4 = (const float4*)(Wm + (size_t)dr*WM_RS + DE);
            float s = 0.f;
            #pragma unroll
            for (int t = 0; t < 8; t++) {
                const float4 w = w4[t*8 + l8];
                const int jb = (t*8 + l8)*4;
                s = fmaf(w.x, sm.misc[jb+0], s); s = fmaf(w.y, sm.misc[jb+1], s);
                s = fmaf(w.z, sm.misc[jb+2], s); s = fmaf(w.w, sm.misc[jb+3], s);
            }
            s += __shfl_down_sync(0xffffffffu, s, 4, 8);
            s += __shfl_down_sync(0xffffffffu, s, 2, 8);
            s += __shfl_down_sync(0xffffffffu, s, 1, 8);
            if (l8 == 0) g_nfb[dr] = s;
        }
    }
    else if (bid < 82) {
        // ---- f0q: 2 query rows of zf[0, 1+i]
        const int qb = (bid - 66) * 2;
        float* xq = sm.misc;
        for (int idx = tid; idx < 2*DD; idx += NT) {
            const int s = idx >> 8, d = idx & 255;
            const int qq = qb + s;
            const int ii = asp_start[qq >> 4] + (qq & 15);
            xq[s*DD + d] = features[(size_t)(1 + ii)*DD + d];
        }
        __syncthreads();
        const int grp = tid >> 3, l8 = tid & 7;
        #pragma unroll
        for (int s = 0; s < 2; s++) {
            const float4* x4 = (const float4*)&xq[s*DD];
            #pragma unroll
            for (int rr = 0; rr < 8; rr++) {
                const int dr = grp*8 + rr;
                const float4* w4 = (const float4*)(Wz + (size_t)dr*DD);
                float o = 0.f;
                #pragma unroll
                for (int t = 0; t < 8; t++) {
                    const float4 w = w4[t*8 + l8], x = x4[t*8 + l8];
                    o = fmaf(w.x, x.x, o); o = fmaf(w.y, x.y, o);
                    o = fmaf(w.z, x.z, o); o = fmaf(w.w, x.w, o);
                }
                o += __shfl_down_sync(0xffffffffu, o, 4, 8);
                o += __shfl_down_sync(0xffffffffu, o, 2, 8);
                o += __shfl_down_sync(0xffffffffu, o, 1, 8);
                if (l8 == 0) g_f0q[(qb + s)*DD + dr] = o + bz[dr];
            }
        }
    }
    else if (bid < 98) {
        // ---- copy features -> out (also warms features in L2 for P1)
        const int cb = bid - 82;
        const float4* src = (const float4*)features;
        float4* d4 = (float4*)out;
        const int total = BB*TP*DD/4;   // 32896
        for (int x = cb*NT + tid; x < total; x += 16*NT) d4[x] = src[x];
    }
    else if (bid < 130) {
        // ---- deterministic adjacency compaction + dep prefetch, one q per block
        const int q = bid - 98;
        const int b = q >> 4;
        const int i = asp_start[b] + (q & 15);
        const int lane = tid & 31, warp = tid >> 5;
        const int pred0 = adj[((size_t)b*MM + i)*MM + tid] != 0;
        const int pred1 = adj[((size_t)b*MM + tid)*MM + i] != 0;
        const unsigned m0 = __ballot_sync(0xffffffffu, pred0);
        const unsigned m1 = __ballot_sync(0xffffffffu, pred1);
        if (lane == 0) s_w[warp] = __popc(m0) + __popc(m1);
        __syncthreads();
        int base = 0;
        #pragma unroll
        for (int w = 0; w < 8; w++) if (w < warp) base += s_w[w];
        const unsigned ltm = (1u << lane) - 1u;
        if (pred0) g_list[q*512 + base + __popc(m0 & ltm)] = tid;
        if (pred1) g_list[q*512 + base + __popc(m0) + __popc(m1 & ltm)] = tid + MM;
        if (tid == 0) {
            int tot = 0;
            #pragma unroll
            for (int w = 0; w < 8; w++) tot += s_w[w];
            g_cnt[q] = tot;
        }
        __syncthreads();
        const int n = g_cnt[q];
        for (int idx = tid; idx < 2*n; idx += NT) {
            const int j = idx >> 1, h = idx & 1;
            const int kk = g_list[q*512 + j];
            const int row = (kk < MM) ? i : kk - MM;
            const int col = (kk < MM) ? kk : i;
            const float* p = dep + (((size_t)b*MM + row)*MM + col)*DE + h*32;
            asm volatile("prefetch.global.L2 [%0];" :: "l"(p));
        }
    }
    else {
        // ---- prefetch Wh (512KB) + Wm_dep lines (64KB) into L2
        const int gidx = (bid - 130)*NT + tid;   // 0..4607
        if (gidx < 4096) {
            asm volatile("prefetch.global.L2 [%0];" :: "l"(Wh + (size_t)gidx*32));
        } else if (gidx < 4096 + 512) {
            const int r = gidx - 4096;
            asm volatile("prefetch.global.L2 [%0];"
                         :: "l"(Wm + (size_t)(r >> 1)*WM_RS + (r & 1)*32));
        }
    }

    gbar();   // ================= barrier 1 =================

    // ================= P1 =================
    if (bid < 128) {
        // ---- nfproj tile: 32 rows x 32 d
        const int r0 = (bid >> 3) * 32;
        const int b = r0 >> 8, ml0 = r0 & 255;
        const int d0 = (bid & 7) * 32;
        const int am = tid & 15, bd = tid >> 4;
        const int ldrow = tid >> 3, ldc = tid & 7;
        u64 acc0 = 0, acc1 = 0;
        for (int jc = 0; jc < 8; jc++) {
            const int j0 = jc * 32;
            const float4 xv = *(const float4*)&features[((size_t)b*TP + 1 + ml0 + ldrow)*DD + j0 + ldc*4];
            const float4 wv = *(const float4*)&g_Wc[(size_t)(j0 + ldrow)*DD + d0 + ldc*4];
            __syncthreads();
            sm.p1.Xs[ldc*4+0][ldrow] = xv.x;
            sm.p1.Xs[ldc*4+1][ldrow] = xv.y;
            sm.p1.Xs[ldc*4+2][ldrow] = xv.z;
            sm.p1.Xs[ldc*4+3][ldrow] = xv.w;
            sm.p1.Ws[ldrow][ldc*4+0] = make_float2(wv.x, wv.x);
            sm.p1.Ws[ldrow][ldc*4+1] = make_float2(wv.y, wv.y);
            sm.p1.Ws[ldrow][ldc*4+2] = make_float2(wv.z, wv.z);
            sm.p1.Ws[ldrow][ldc*4+3] = make_float2(wv.w, wv.w);
            __syncthreads();
            #pragma unroll
            for (int j = 0; j < 32; j++) {
                const u64 x2 = *(const u64*)&sm.p1.Xs[j][2*am];
                const u64 w0 = *(const u64*)&sm.p1.Ws[j][2*bd];
                const u64 w1 = *(const u64*)&sm.p1.Ws[j][2*bd+1];
                acc0 = ffma2(x2, w0, acc0);
                acc1 = ffma2(x2, w1, acc1);
            }
        }
        const float2 a0 = unpack2(acc0), a1 = unpack2(acc1);
        const int dA = d0 + 2*bd, dB = dA + 1;
        const float nbA = g_nfb[dA], nbB = g_nfb[dB];
        const size_t rowbase = ((size_t)b*MM + ml0 + 2*am)*DD;
        g_nfproj[rowbase + dA]      = a0.x + nbA;
        g_nfproj[rowbase + DD + dA] = a0.y + nbA;
        g_nfproj[rowbase + dB]      = a1.x + nbB;
        g_nfproj[rowbase + DD + dB] = a1.y + nbB;
    }
    else if (bid < 132) {
        // ---- nfdot: 128 rows per block, 8-lane dots against u
        const int r0 = (bid - 128) * 128;
        sm.misc[tid] = g_u[tid];
        __syncthreads();
        const float c1 = g_c1[0];
        const float4* us4 = (const float4*)sm.misc;
        const int rg8 = tid >> 3, l8 = tid & 7;
        for (int pass = 0; pass < 4; pass++) {
            const int row = r0 + pass*32 + rg8;
            const int b = row >> 8, ml = row & 255;
            const float4* x4 = (const float4*)&features[((size_t)b*TP + 1 + ml)*DD];
            float s = 0.f;
            #pragma unroll
            for (int t = 0; t < 8; t++) {
                const float4 x = x4[t*8 + l8], u = us4[t*8 + l8];
                s = fmaf(x.x, u.x, s); s = fmaf(x.y, u.y, s);
                s = fmaf(x.z, u.z, s); s = fmaf(x.w, u.w, s);
            }
            s += __shfl_down_sync(0xffffffffu, s, 4, 8);
            s += __shfl_down_sync(0xffffffffu, s, 2, 8);
            s += __shfl_down_sync(0xffffffffu, s, 1, 8);
            if (l8 == 0) g_nfdot[b*MM + ml] = s + c1;
        }
    }

    gbar();   // ================= barrier 2 =================

    // ================= P2: scores + softmax + message =================
    if (bid < 128) {
        const int q = bid >> 2, dc = bid & 3;
        const int b = q >> 4;
        const int i = asp_start[b] + (q & 15);
        const int n = g_cnt[q];

        for (int idx = tid; idx < n; idx += NT) sm.p2.list[idx] = g_list[q*512 + idx];
        if (tid < DE) sm.p2.wdep[tid] = Wa[tid];
        __syncthreads();

        const float aspdot = bsum256(g_f0q[q*DD + tid] * Wa[DE + DD + tid], s_red);

        // scores (chunked staging)
        for (int c0 = 0; c0 < n; c0 += 96) {
            const int nc = min(96, n - c0);
            __syncthreads();
            for (int idx = tid; idx < nc*16; idx += NT) {
                const int j = idx >> 4, e4 = idx & 15;
                const int kk = sm.p2.list[c0 + j];
                const int row = (kk < MM) ? i : kk - MM;
                const int col = (kk < MM) ? kk : i;
                *(float4*)&sm.p2.dsr[j][e4*4] =
                    ((const float4*)dep)[(((size_t)b*MM + row)*MM + col)*16 + e4];
            }
            __syncthreads();
            for (int j = tid; j < nc; j += NT) {
                float s = 0.f;
                #pragma unroll
                for (int e4 = 0; e4 < 16; e4++) {
                    const float4 v = *(const float4*)&sm.p2.dsr[j][e4*4];
                    s = fmaf(v.x, sm.p2.wdep[4*e4+0], s); s = fmaf(v.y, sm.p2.wdep[4*e4+1], s);
                    s = fmaf(v.z, sm.p2.wdep[4*e4+2], s); s = fmaf(v.w, sm.p2.wdep[4*e4+3], s);
                }
                const int kk = sm.p2.list[c0 + j];
                s += g_nfdot[b*MM + (kk & (MM-1))] + aspdot;
                sm.p2.s_l[c0 + j] = (s > 0.f) ? s : 0.01f * s;
            }
        }
        __syncthreads();

        // softmax over n
        const float sv0 = (tid      < n) ? sm.p2.s_l[tid]       : -FLT_MAX;
        const float sv1 = (tid + NT < n) ? sm.p2.s_l[tid + NT]  : -FLT_MAX;
        const float smax = bmax256(fmaxf(sv0, sv1), s_red);
        const float e0 = (tid      < n) ? expf(sv0 - smax) : 0.f;
        const float e1 = (tid + NT < n) ? expf(sv1 - smax) : 0.f;
        if (tid      < n) sm.p2.wn[tid]      = e0;
        if (tid + NT < n) sm.p2.wn[tid + NT] = e1;
        const float inv = 1.f / bsum256(e0 + e1, s_red);

        // message for d = dc*64 + dl
        const int kg = tid >> 6, dl = tid & 63;
        const int d  = dc*64 + dl;
        u64 wp[32];
        {
            const ulonglong2* w2 = (const ulonglong2*)(Wm + (size_t)d*WM_RS);
            #pragma unroll
            for (int t2 = 0; t2 < 16; t2++) {
                const ulonglong2 v = w2[t2];
                wp[2*t2] = v.x; wp[2*t2 + 1] = v.y;
            }
        }
        float acc = 0.f;
        for (int c0 = 0; c0 < n; c0 += 96) {
            const int nc = min(96, n - c0);
            __syncthreads();
            for (int idx = tid; idx < nc*16; idx += NT) {
                const int j = idx >> 4, e4 = idx & 15;
                const int kk = sm.p2.list[c0 + j];
                const int row = (kk < MM) ? i : kk - MM;
                const int col = (kk < MM) ? kk : i;
                *(float4*)&sm.p2.dsr[j][e4*4] =
                    ((const float4*)dep)[(((size_t)b*MM + row)*MM + col)*16 + e4];
            }
            __syncthreads();
            for (int jl = kg; jl < nc; jl += 4) {
                const int pos = c0 + jl;
                const int kk  = sm.p2.list[pos];
                const float wk = sm.p2.wn[pos] * inv;
                const float mi = g_nfproj[((size_t)b*MM + (kk & (MM-1)))*DD + d];
                const ulonglong2* dr2 = (const ulonglong2*)&sm.p2.dsr[jl][0];
                u64 mA = 0, mB = 0, mC = 0, mD = 0;
                #pragma unroll
                for (int t2 = 0; t2 < 16; t2 += 2) {
                    const ulonglong2 v0 = dr2[t2];
                    const ulonglong2 v1 = dr2[t2 + 1];
                    mA = ffma2(v0.x, wp[2*t2],     mA);
                    mB = ffma2(v0.y, wp[2*t2 + 1], mB);
                    mC = ffma2(v1.x, wp[2*t2 + 2], mC);
                    mD = ffma2(v1.y, wp[2*t2 + 3], mD);
                }
                const float2 sA = unpack2(mA), sB = unpack2(mB);
                const float2 sC = unpack2(mC), sD = unpack2(mD);
                const float mval = mi + ((sA.x + sA.y) + (sB.x + sB.y))
                                      + ((sC.x + sC.y) + (sD.x + sD.y));
                acc = fmaf(wk, fmaxf(mval, 0.f), acc);
            }
        }
        sm.p2.fpart[kg][dl] = acc;
        __syncthreads();
        if (tid < 64)
            g_fused[q*DD + dc*64 + tid] = sm.p2.fpart[0][tid] + sm.p2.fpart[1][tid]
                                        + sm.p2.fpart[2][tid] + sm.p2.fpart[3][tid];
    }

    gbar();   // ================= barrier 3 =================

    // ================= P3: output head (256 tasks) =================
    for (int t = bid; t < 256; t += GRID) {
        const int q = t >> 3, rg = t & 7;
        const int b = q >> 4;
        const int i = asp_start[b] + (q & 15);
        __syncthreads();
        sm.cat[tid]      = g_fused[q*DD + tid];
        sm.cat[DD + tid] = g_f0q[q*DD + tid];
        __syncthreads();

        const int warp = tid >> 5, lane = tid & 31;
        const int rsub = lane >> 3, l8 = lane & 7;
        const int dr = rg*32 + warp*4 + rsub;
        const ulonglong2* wrow = (const ulonglong2*)(Wh + (size_t)dr*2*DD);
        const ulonglong2* cat2 = (const ulonglong2*)sm.cat;
        u64 oA = 0, oB = 0;
        #pragma unroll
        for (int tt = 0; tt < 16; tt++) {
            const int idx = tt*8 + l8;
            const ulonglong2 wv = wrow[idx];
            const ulonglong2 cv = cat2[idx];
            oA = ffma2(wv.x, cv.x, oA);
            oB = ffma2(wv.y, cv.y, oB);
        }
        const float2 a = unpack2(oA), bb = unpack2(oB);
        float o = (a.x + a.y) + (bb.x + bb.y);
        o += __shfl_down_sync(0xffffffffu, o, 4, 8);
        o += __shfl_down_sync(0xffffffffu, o, 2, 8);
        o += __shfl_down_sync(0xffffffffu, o, 1, 8);
        if (l8 == 0)
            out[((size_t)b*TP + 1 + i)*DD + dr] = fmaxf(o, 0.f);
    }
}

// ---------------- launcher ----------------
extern "C" void kernel_launch(void* const* d_in, const int* in_sizes, int n_in,
                              void* d_out, int out_size)
{
    const float* features  = (const float*)d_in[0];
    const float* dep       = (const float*)d_in[1];
    const int*   adj       = (const int*)  d_in[2];
    const int*   asp_start = (const int*)  d_in[3];
    const float* Wz        = (const float*)d_in[5];
    const float* bz        = (const float*)d_in[6];
    const float* Wa        = (const float*)d_in[7];
    const float* Wm        = (const float*)d_in[8];
    const float* Wh        = (const float*)d_in[9];
    float* out = (float*)d_out;

    fused_all<<<GRID, NT>>>(features, dep, adj, asp_start,
                            Wz, bz, Wa, Wm, Wh, out);
}